// round 1
// baseline (speedup 1.0000x reference)
#include <cuda_runtime.h>
#include <cuda_bf16.h>
#include <math.h>

#define BATCH 128
#define NTQ   512
#define NCK   512
#define EMB   256
#define DK    60
#define NTOK  (BATCH*NCK)

// Scratch (allocation-free: device globals)
__device__ float g_K[NTOK*DK];
__device__ float g_V[NTOK*DK];
__device__ float g_kn[NTOK];

// ---------------------------------------------------------------------------
// Kernel 1: K/V projection + key norms.
// Block = 32 context tokens, 256 threads (8 warps).
// Warp w (0..3) computes K dims [w*15, w*15+15); warp w (4..7) computes V dims.
// lane = token. Weight reads are warp-uniform (broadcast); emb reads are
// LDS.128 from a 260-float-stride smem tile (effectively conflict-free).
// ---------------------------------------------------------------------------
__global__ __launch_bounds__(256) void kv_proj_kernel(
    const int* __restrict__ citems, const float* __restrict__ cvec,
    const float* __restrict__ Acw, const float* __restrict__ Acb,
    const float* __restrict__ Bcw, const float* __restrict__ Bcb)
{
    __shared__ float emb[32*260];
    __shared__ float sq[4][32];
    __shared__ int items[32];

    const int t = threadIdx.x, lane = t & 31, w = t >> 5;
    const int base = blockIdx.x * 32;

    if (t < 32) items[t] = citems[base + t];
    __syncthreads();

    // gather: 4 rows per warp, float4 coalesced
    for (int r = w*4; r < w*4 + 4; r++) {
        const float4* src = (const float4*)(cvec + (size_t)items[r]*EMB);
        float4* dst = (float4*)(emb + r*260);
        #pragma unroll
        for (int i = lane; i < 64; i += 32) dst[i] = src[i];
    }
    __syncthreads();

    const bool isK = (w < 4);
    const float* Wm = isK ? Acw : Bcw;
    const float* Bm = isK ? Acb : Bcb;
    float* Gm = isK ? g_K : g_V;
    const int dbase = (w & 3) * 15;
    const float4* e4 = (const float4*)(emb + lane*260);
    const int gi = base + lane;
    float ss = 0.f;

    #pragma unroll
    for (int g = 0; g < 5; g++) {
        const int d0 = dbase + g*3;
        const float4* w0 = (const float4*)(Wm + (d0+0)*EMB);
        const float4* w1 = (const float4*)(Wm + (d0+1)*EMB);
        const float4* w2 = (const float4*)(Wm + (d0+2)*EMB);
        float s0 = Bm[d0+0], s1 = Bm[d0+1], s2 = Bm[d0+2];
        #pragma unroll 8
        for (int i = 0; i < 64; i++) {
            float4 ev = e4[i];
            float4 a = w0[i], b4 = w1[i], c4 = w2[i];
            s0 += ev.x*a.x  + ev.y*a.y  + ev.z*a.z  + ev.w*a.w;
            s1 += ev.x*b4.x + ev.y*b4.y + ev.z*b4.z + ev.w*b4.w;
            s2 += ev.x*c4.x + ev.y*c4.y + ev.z*c4.z + ev.w*c4.w;
        }
        Gm[gi*60 + d0+0] = s0;
        Gm[gi*60 + d0+1] = s1;
        Gm[gi*60 + d0+2] = s2;
        ss += s0*s0 + s1*s1 + s2*s2;
    }

    if (isK) sq[w][lane] = ss;
    __syncthreads();
    if (t < 32) g_kn[base + t] = sqrtf(sq[0][t] + sq[1][t] + sq[2][t] + sq[3][t]);
}

// ---------------------------------------------------------------------------
// Kernel 2: fused Q-projection + cosine attention + output projection.
// Block = (batch b, 64-query tile). 256 threads.
// Softmax without max-subtraction: scores = cos_sim (|.|<=1) + tiny bias,
// so expf is in [0.36, 2.73] — no overflow possible.
// ---------------------------------------------------------------------------
// smem layout (floats):
#define S_QS 0            // 64*65
#define S_QN 4160         // 64
#define S_L  4224         // 64
#define S_KN 4288         // 64
#define S_PB 4352         // 64
#define S_IT 4416         // 64 (int)
#define S_SQ 4480         // 256
#define S_B  4736         // union region: qemb(64*260) OR the 5 tiles below
#define S_KS (S_B)
#define S_VS (S_B+4160)
#define S_PS (S_B+8320)
#define S_OS (S_B+12480)
#define S_RW (S_B+16640)
#define SMEM_FLOATS (S_B+20800)
#define ATT_SMEM_BYTES (SMEM_FLOATS*4)

__global__ __launch_bounds__(256) void att_kernel(
    const int* __restrict__ titems, const float* __restrict__ tvec,
    const float* __restrict__ Atw, const float* __restrict__ Atb,
    const float* __restrict__ pos_bias,
    const float* __restrict__ Rw, const float* __restrict__ Rb,
    float* __restrict__ out)
{
    extern __shared__ float sm[];
    const int t = threadIdx.x, lane = t & 31, w = t >> 5;
    const int b  = blockIdx.x >> 3;
    const int qt = blockIdx.x & 7;
    const int tok0 = b*NTQ + qt*64;

    int* it_s = (int*)(sm + S_IT);
    if (t < 64) it_s[t] = titems[tok0 + t];
    __syncthreads();

    // gather 64 query embedding rows into qemb (region B)
    float* qemb = sm + S_B;
    for (int r = w*8; r < w*8 + 8; r++) {
        const float4* src = (const float4*)(tvec + (size_t)it_s[r]*EMB);
        float4* dst = (float4*)(qemb + r*260);
        #pragma unroll
        for (int i = lane; i < 64; i += 32) dst[i] = src[i];
    }
    __syncthreads();

    // Q projection: warp w -> token half (w&1), dim group (w>>1)*15
    {
        const int tok = (w & 1)*32 + lane;
        const int dbase = (w >> 1)*15;
        const float4* e4 = (const float4*)(qemb + tok*260);
        float ss = 0.f;
        #pragma unroll
        for (int g = 0; g < 5; g++) {
            const int d0 = dbase + g*3;
            const float4* w0 = (const float4*)(Atw + (d0+0)*EMB);
            const float4* w1 = (const float4*)(Atw + (d0+1)*EMB);
            const float4* w2 = (const float4*)(Atw + (d0+2)*EMB);
            float s0 = Atb[d0+0], s1 = Atb[d0+1], s2 = Atb[d0+2];
            #pragma unroll 8
            for (int i = 0; i < 64; i++) {
                float4 ev = e4[i];
                float4 a = w0[i], b4 = w1[i], c4 = w2[i];
                s0 += ev.x*a.x  + ev.y*a.y  + ev.z*a.z  + ev.w*a.w;
                s1 += ev.x*b4.x + ev.y*b4.y + ev.z*b4.z + ev.w*b4.w;
                s2 += ev.x*c4.x + ev.y*c4.y + ev.z*c4.z + ev.w*c4.w;
            }
            sm[S_QS + tok*65 + d0+0] = s0;
            sm[S_QS + tok*65 + d0+1] = s1;
            sm[S_QS + tok*65 + d0+2] = s2;
            ss += s0*s0 + s1*s1 + s2*s2;
        }
        sm[S_SQ + (w>>1)*64 + tok] = ss;
    }
    __syncthreads();
    if (t < 64) {
        sm[S_QN + t] = sqrtf(sm[S_SQ+t] + sm[S_SQ+64+t] + sm[S_SQ+128+t] + sm[S_SQ+192+t]);
        sm[S_L + t] = 0.f;
        sm[S_QS + t*65 + 60] = 0.f; sm[S_QS + t*65 + 61] = 0.f;
        sm[S_QS + t*65 + 62] = 0.f; sm[S_QS + t*65 + 63] = 0.f;
    }
    __syncthreads();   // qemb dead from here; region B reused for tiles

    const int qg = t & 15;   // query group (4 queries)
    const int sg = t >> 4;   // secondary group: kg / dg / eg per phase

    float oa[16];
    #pragma unroll
    for (int z = 0; z < 16; z++) oa[z] = 0.f;

    for (int kt = 0; kt < 8; kt++) {
        // load K/V tile (zero-padded to 64 cols), key norms, pos bias
        {
            const size_t gbase = (size_t)(b*NCK + kt*64) * 60;
            for (int idx = t; idx < 4096; idx += 256) {
                const int r = idx >> 6, c = idx & 63;
                const bool v = (c < 60);
                const size_t gidx = gbase + (size_t)r*60 + c;
                sm[S_KS + r*65 + c] = v ? g_K[gidx] : 0.f;
                sm[S_VS + r*65 + c] = v ? g_V[gidx] : 0.f;
            }
            if (t < 64) {
                sm[S_KN + t] = g_kn[b*NCK + kt*64 + t];
                sm[S_PB + t] = pos_bias[kt*64 + t];
            }
        }
        __syncthreads();

        // scores: 4x4 register tile, then normalize + exp -> Ps
        {
            float sa[16];
            #pragma unroll
            for (int z = 0; z < 16; z++) sa[z] = 0.f;
            const float* Qp = sm + S_QS + qg*4*65;
            const float* Kp = sm + S_KS + sg*4*65;
            #pragma unroll 4
            for (int d = 0; d < 64; d++) {
                const float q0 = Qp[d], q1 = Qp[65+d], q2 = Qp[130+d], q3 = Qp[195+d];
                const float k0 = Kp[d], k1 = Kp[65+d], k2 = Kp[130+d], k3 = Kp[195+d];
                sa[0] += q0*k0; sa[1] += q0*k1; sa[2]  += q0*k2; sa[3]  += q0*k3;
                sa[4] += q1*k0; sa[5] += q1*k1; sa[6]  += q1*k2; sa[7]  += q1*k3;
                sa[8] += q2*k0; sa[9] += q2*k1; sa[10] += q2*k2; sa[11] += q2*k3;
                sa[12]+= q3*k0; sa[13]+= q3*k1; sa[14] += q3*k2; sa[15] += q3*k3;
            }
            #pragma unroll
            for (int i = 0; i < 4; i++) {
                const float qnv = sm[S_QN + qg*4 + i];
                #pragma unroll
                for (int j = 0; j < 4; j++) {
                    const int k = sg*4 + j;
                    const float den = fmaxf(qnv * sm[S_KN + k], 1e-6f);
                    const float p = __expf(sa[i*4+j] / den + sm[S_PB + k]);
                    sm[S_PS + (qg*4+i)*65 + k] = p;
                }
            }
        }
        __syncthreads();

        // PV: 4x4 register tile accumulated across key tiles
        {
            const float* Pp = sm + S_PS + qg*4*65;
            const float* Vp = sm + S_VS + sg*4;
            #pragma unroll 4
            for (int k = 0; k < 64; k++) {
                const float p0 = Pp[k], p1 = Pp[65+k], p2 = Pp[130+k], p3 = Pp[195+k];
                const float v0 = Vp[k*65+0], v1 = Vp[k*65+1], v2 = Vp[k*65+2], v3 = Vp[k*65+3];
                oa[0] += p0*v0; oa[1] += p0*v1; oa[2]  += p0*v2; oa[3]  += p0*v3;
                oa[4] += p1*v0; oa[5] += p1*v1; oa[6]  += p1*v2; oa[7]  += p1*v3;
                oa[8] += p2*v0; oa[9] += p2*v1; oa[10] += p2*v2; oa[11] += p2*v3;
                oa[12]+= p3*v0; oa[13]+= p3*v1; oa[14] += p3*v2; oa[15] += p3*v3;
            }
        }
        // partial row-sums of Ps for softmax denominator
        {
            const int q = t >> 2, q4 = t & 3;
            const float* Pq = sm + S_PS + q*65 + q4*16;
            float s = 0.f;
            #pragma unroll
            for (int j = 0; j < 16; j++) s += Pq[j];
            sm[S_SQ + q4*64 + q] = s;
        }
        __syncthreads();
        if (t < 64)
            sm[S_L + t] += sm[S_SQ+t] + sm[S_SQ+64+t] + sm[S_SQ+128+t] + sm[S_SQ+192+t];
    }
    __syncthreads();

    // finalize: Os = oa / l   (cols 60..63 are naturally 0)
    {
        const float i0 = 1.f/sm[S_L + qg*4+0], i1 = 1.f/sm[S_L + qg*4+1];
        const float i2 = 1.f/sm[S_L + qg*4+2], i3 = 1.f/sm[S_L + qg*4+3];
        #pragma unroll
        for (int j = 0; j < 4; j++) {
            sm[S_OS + (qg*4+0)*65 + sg*4+j] = oa[0*4+j]*i0;
            sm[S_OS + (qg*4+1)*65 + sg*4+j] = oa[1*4+j]*i1;
            sm[S_OS + (qg*4+2)*65 + sg*4+j] = oa[2*4+j]*i2;
            sm[S_OS + (qg*4+3)*65 + sg*4+j] = oa[3*4+j]*i3;
        }
    }
    __syncthreads();

    // output projection: out(64 x 256) = Os(64x60) @ Rw^T, in 4 passes of 64 cols
    for (int pass = 0; pass < 4; pass++) {
        const int e0 = pass*64;
        for (int idx = t; idx < 4096; idx += 256) {
            const int r = idx >> 6, c = idx & 63;
            sm[S_RW + r*65 + c] = (c < 60) ? Rw[(e0+r)*60 + c] : 0.f;
        }
        __syncthreads();

        float oc[16];
        #pragma unroll
        for (int z = 0; z < 16; z++) oc[z] = 0.f;
        const float* Op = sm + S_OS + qg*4*65;
        const float* Rp = sm + S_RW + sg*4*65;
        #pragma unroll 4
        for (int d = 0; d < 64; d++) {
            const float o0 = Op[d], o1 = Op[65+d], o2 = Op[130+d], o3 = Op[195+d];
            const float r0 = Rp[d], r1 = Rp[65+d], r2 = Rp[130+d], r3 = Rp[195+d];
            oc[0] += o0*r0; oc[1] += o0*r1; oc[2]  += o0*r2; oc[3]  += o0*r3;
            oc[4] += o1*r0; oc[5] += o1*r1; oc[6]  += o1*r2; oc[7]  += o1*r3;
            oc[8] += o2*r0; oc[9] += o2*r1; oc[10] += o2*r2; oc[11] += o2*r3;
            oc[12]+= o3*r0; oc[13]+= o3*r1; oc[14] += o3*r2; oc[15] += o3*r3;
        }
        #pragma unroll
        for (int i = 0; i < 4; i++)
            #pragma unroll
            for (int j = 0; j < 4; j++)
                sm[S_PS + (qg*4+i)*65 + sg*4+j] = oc[i*4+j];
        __syncthreads();

        for (int idx = t; idx < 4096; idx += 256) {
            const int r = idx >> 6, c = idx & 63;
            out[(size_t)(tok0 + r)*EMB + e0 + c] = sm[S_PS + r*65 + c] + Rb[e0 + c];
        }
        __syncthreads();
    }
}

// ---------------------------------------------------------------------------
extern "C" void kernel_launch(void* const* d_in, const int* in_sizes, int n_in,
                              void* d_out, int out_size)
{
    (void)in_sizes; (void)n_in; (void)out_size;
    const int*   titems = (const int*)  d_in[0];
    const int*   citems = (const int*)  d_in[1];
    const float* tvec   = (const float*)d_in[2];
    const float* cvec   = (const float*)d_in[3];
    const float* Atw    = (const float*)d_in[4];
    const float* Atb    = (const float*)d_in[5];
    const float* Acw    = (const float*)d_in[6];
    const float* Acb    = (const float*)d_in[7];
    const float* Bcw    = (const float*)d_in[8];
    const float* Bcb    = (const float*)d_in[9];
    const float* pb     = (const float*)d_in[10];
    const float* Rw     = (const float*)d_in[11];
    const float* Rb     = (const float*)d_in[12];
    float* out = (float*)d_out;

    kv_proj_kernel<<<NTOK/32, 256>>>(citems, cvec, Acw, Acb, Bcw, Bcb);

    cudaFuncSetAttribute(att_kernel, cudaFuncAttributeMaxDynamicSharedMemorySize,
                         ATT_SMEM_BYTES);
    att_kernel<<<BATCH*(NTQ/64), 256, ATT_SMEM_BYTES>>>(
        titems, tvec, Atw, Atb, pb, Rw, Rb, out);
}

// round 4
// speedup vs baseline: 1.1668x; 1.1668x over previous
#include <cuda_runtime.h>
#include <math.h>

#define BATCH 128
#define NTQ   512
#define NCK   512
#define EMB   256
#define DK    60
#define NTOK  (BATCH*NCK)

typedef unsigned long long ull;

// packed f32x2 FMA (sm_100a): d = a*b + c on two fp32 lanes
__device__ __forceinline__ ull fma2(ull a, ull b, ull c) {
    ull d;
    asm("fma.rn.f32x2 %0, %1, %2, %3;" : "=l"(d) : "l"(a), "l"(b), "l"(c));
    return d;
}
__device__ __forceinline__ float f2lo(ull x){ return __uint_as_float((unsigned)x); }
__device__ __forceinline__ float f2hi(ull x){ return __uint_as_float((unsigned)(x>>32)); }
__device__ __forceinline__ float hadd2(ull x){ return f2lo(x)+f2hi(x); }

// Scratch (allocation-free: device globals)
__device__ float g_K[NTOK*DK];
__device__ float g_V[NTOK*DK];
__device__ float g_kn[NTOK];

// ---------------------------------------------------------------------------
// Kernel 1: K/V projection + key norms. Block = 32 ctx tokens, 256 threads.
// Warps 0-3: K dims w*15..+15; warps 4-7: V dims. f32x2 inner loop.
// ---------------------------------------------------------------------------
__global__ __launch_bounds__(256) void kv_proj_kernel(
    const int* __restrict__ citems, const float* __restrict__ cvec,
    const float* __restrict__ Acw, const float* __restrict__ Acb,
    const float* __restrict__ Bcw, const float* __restrict__ Bcb)
{
    __shared__ float emb[32*260];
    __shared__ float sq[4][32];
    __shared__ int items[32];

    const int t = threadIdx.x, lane = t & 31, w = t >> 5;
    const int base = blockIdx.x * 32;

    if (t < 32) items[t] = citems[base + t];
    __syncthreads();

    for (int r = w*4; r < w*4 + 4; r++) {
        const float4* src = (const float4*)(cvec + (size_t)items[r]*EMB);
        float4* dst = (float4*)(emb + r*260);
        #pragma unroll
        for (int i = lane; i < 64; i += 32) dst[i] = src[i];
    }
    __syncthreads();

    const bool isK = (w < 4);
    const float* Wm = isK ? Acw : Bcw;
    const float* Bm = isK ? Acb : Bcb;
    float* Gm = isK ? g_K : g_V;
    const int dbase = (w & 3) * 15;
    const ulonglong2* e2 = (const ulonglong2*)(emb + lane*260);
    const int gi = base + lane;
    float ss = 0.f;

    #pragma unroll
    for (int g = 0; g < 5; g++) {
        const int d0 = dbase + g*3;
        const ulonglong2* w0 = (const ulonglong2*)(Wm + (d0+0)*EMB);
        const ulonglong2* w1 = (const ulonglong2*)(Wm + (d0+1)*EMB);
        const ulonglong2* w2 = (const ulonglong2*)(Wm + (d0+2)*EMB);
        ull a0 = 0, a1 = 0, a2 = 0;
        #pragma unroll 8
        for (int i = 0; i < 64; i++) {
            ulonglong2 e = e2[i];
            ulonglong2 p0 = w0[i], p1 = w1[i], p2 = w2[i];
            a0 = fma2(e.x, p0.x, a0); a0 = fma2(e.y, p0.y, a0);
            a1 = fma2(e.x, p1.x, a1); a1 = fma2(e.y, p1.y, a1);
            a2 = fma2(e.x, p2.x, a2); a2 = fma2(e.y, p2.y, a2);
        }
        float s0 = hadd2(a0) + Bm[d0+0];
        float s1 = hadd2(a1) + Bm[d0+1];
        float s2 = hadd2(a2) + Bm[d0+2];
        Gm[gi*60 + d0+0] = s0;
        Gm[gi*60 + d0+1] = s1;
        Gm[gi*60 + d0+2] = s2;
        ss += s0*s0 + s1*s1 + s2*s2;
    }

    if (isK) sq[w][lane] = ss;
    __syncthreads();
    if (t < 32) g_kn[base + t] = sqrtf(sq[0][t] + sq[1][t] + sq[2][t] + sq[3][t]);
}

// ---------------------------------------------------------------------------
// Kernel 2: fused Q-proj + cosine attention + output projection.
// All GEMM operands in d-pair interleaved smem layout [d/2][col*2+(d&1)],
// rows padded to 132 floats, so LDS.128 yields two f32x2 operands directly.
// ---------------------------------------------------------------------------
#define RS 132                 // row stride (floats) of pair-layout tiles
#define S_Qp 0                 // 32 x 132
#define S_Kp 4224
#define S_Vp 8448
#define S_Pp 12672             // also reused as output staging tile (64x66)
#define S_Op 16896
#define S_Rw 21120
#define S_SC 25344
#define S_QN (S_SC)            // 64
#define S_L  (S_SC+64)         // 64
#define S_KN (S_SC+128)        // 64
#define S_PB (S_SC+192)        // 64
#define S_IT (S_SC+256)        // 64 ints
#define S_SQ (S_SC+320)        // 256
#define SMEM_FLOATS (S_SC+576)
#define ATT_SMEM_BYTES (SMEM_FLOATS*4)

__global__ __launch_bounds__(256, 2) void att_kernel(
    const int* __restrict__ titems, const float* __restrict__ tvec,
    const float* __restrict__ Atw, const float* __restrict__ Atb,
    const float* __restrict__ pos_bias,
    const float* __restrict__ Rw, const float* __restrict__ Rb,
    float* __restrict__ out)
{
    extern __shared__ float sm[];
    const int t = threadIdx.x, lane = t & 31, w = t >> 5;
    const int b  = blockIdx.x >> 3;
    const int qt = blockIdx.x & 7;
    const int tok0 = b*NTQ + qt*64;

    int* it_s = (int*)(sm + S_IT);
    if (t < 64) it_s[t] = titems[tok0 + t];
    __syncthreads();

    // gather 64 query embedding rows (staged in the Kp..Op region)
    float* qemb = sm + S_Kp;
    for (int r = w*8; r < w*8 + 8; r++) {
        const float4* src = (const float4*)(tvec + (size_t)it_s[r]*EMB);
        float4* dst = (float4*)(qemb + r*260);
        #pragma unroll
        for (int i = lane; i < 64; i += 32) dst[i] = src[i];
    }
    __syncthreads();

    // Q projection -> pair layout Qp[d>>1][tok*2+(d&1)], f32x2 inner loop
    {
        const int tok = (w & 1)*32 + lane;
        const int dbase = (w >> 1)*15;
        const ulonglong2* e2 = (const ulonglong2*)(qemb + tok*260);
        float ss = 0.f;
        #pragma unroll
        for (int g = 0; g < 5; g++) {
            const int d0 = dbase + g*3;
            const ulonglong2* w0 = (const ulonglong2*)(Atw + (d0+0)*EMB);
            const ulonglong2* w1 = (const ulonglong2*)(Atw + (d0+1)*EMB);
            const ulonglong2* w2 = (const ulonglong2*)(Atw + (d0+2)*EMB);
            ull a0 = 0, a1 = 0, a2 = 0;
            #pragma unroll 8
            for (int i = 0; i < 64; i++) {
                ulonglong2 e = e2[i];
                ulonglong2 p0 = w0[i], p1 = w1[i], p2 = w2[i];
                a0 = fma2(e.x, p0.x, a0); a0 = fma2(e.y, p0.y, a0);
                a1 = fma2(e.x, p1.x, a1); a1 = fma2(e.y, p1.y, a1);
                a2 = fma2(e.x, p2.x, a2); a2 = fma2(e.y, p2.y, a2);
            }
            float s0 = hadd2(a0) + Atb[d0+0];
            float s1 = hadd2(a1) + Atb[d0+1];
            float s2 = hadd2(a2) + Atb[d0+2];
            sm[S_Qp + ((d0+0)>>1)*RS + tok*2 + ((d0+0)&1)] = s0;
            sm[S_Qp + ((d0+1)>>1)*RS + tok*2 + ((d0+1)&1)] = s1;
            sm[S_Qp + ((d0+2)>>1)*RS + tok*2 + ((d0+2)&1)] = s2;
            ss += s0*s0 + s1*s1 + s2*s2;
        }
        sm[S_SQ + (w>>1)*64 + tok] = ss;
    }
    __syncthreads();
    if (t < 64) {
        sm[S_QN + t] = sqrtf(sm[S_SQ+t] + sm[S_SQ+64+t] + sm[S_SQ+128+t] + sm[S_SQ+192+t]);
        sm[S_L + t] = 0.f;
    }
    // zero pads: Qp/Kp/Rw rows 30,31 (d>=60); Vp cols 120..127 (dv>=60)
    for (int idx = t; idx < 264; idx += 256) {
        sm[S_Qp + 30*RS + idx] = 0.f;
        sm[S_Kp + 30*RS + idx] = 0.f;
        sm[S_Rw + 30*RS + idx] = 0.f;
    }
    {
        int r = t >> 3, c = t & 7;
        if (r < 32) sm[S_Vp + r*RS + 120 + c] = 0.f;
    }
    __syncthreads();

    const int qg = t & 15;   // 4 queries: qg*2, qg*2+1, qg*2+32, qg*2+33
    const int sg = t >> 4;   // 4 keys / dv / emb cols, same pattern

    const int q0 = qg*2, q1 = qg*2+1, q2 = qg*2+32, q3 = qg*2+33;
    const int k0 = sg*2, k1 = sg*2+1, k2i = sg*2+32, k3 = sg*2+33;

    ull oacc[16];
    #pragma unroll
    for (int z = 0; z < 16; z++) oacc[z] = 0;

    const ulonglong2* Qa = (const ulonglong2*)(sm + S_Qp + qg*4);
    const ulonglong2* Qb = (const ulonglong2*)(sm + S_Qp + qg*4 + 64);
    const ulonglong2* Ka = (const ulonglong2*)(sm + S_Kp + sg*4);
    const ulonglong2* Kb = (const ulonglong2*)(sm + S_Kp + sg*4 + 64);
    const ulonglong2* Pa = (const ulonglong2*)(sm + S_Pp + qg*4);
    const ulonglong2* Pb = (const ulonglong2*)(sm + S_Pp + qg*4 + 64);
    const ulonglong2* Va = (const ulonglong2*)(sm + S_Vp + sg*4);
    const ulonglong2* Vb = (const ulonglong2*)(sm + S_Vp + sg*4 + 64);

    for (int kt = 0; kt < 8; kt++) {
        // ---- load K/V tile into pair layouts ----
        {
            const size_t gb = (size_t)(b*NCK + kt*64) * 60;
            const float2* Ksrc = (const float2*)(g_K + gb);
            const float2* Vsrc = (const float2*)(g_V + gb);
            for (int idx = t; idx < 1920; idx += 256) {
                const int r = idx / 30;            // key row 0..63
                const int c = (idx - r*30) * 2;    // dim 0..58 even
                float2 kv = Ksrc[idx];
                *(float2*)(sm + S_Kp + (c>>1)*RS + r*2) = kv;   // [d2][k*2+(d&1)]
                float2 vv = Vsrc[idx];
                sm[S_Vp + (r>>1)*RS + c*2     + (r&1)] = vv.x;  // [k2][dv*2+(k&1)]
                sm[S_Vp + (r>>1)*RS + (c+1)*2 + (r&1)] = vv.y;
            }
            if (t < 64) {
                sm[S_KN + t] = g_kn[b*NCK + kt*64 + t];
                sm[S_PB + t] = pos_bias[kt*64 + t];
            }
        }
        __syncthreads();

        // ---- scores: contraction over d via f32x2 lanes ----
        {
            ull acc[16];
            #pragma unroll
            for (int z = 0; z < 16; z++) acc[z] = 0;
            #pragma unroll 4
            for (int d2 = 0; d2 < 32; d2++) {
                ulonglong2 qa = Qa[d2*33], qb = Qb[d2*33];
                ulonglong2 ka = Ka[d2*33], kb = Kb[d2*33];
                acc[0] = fma2(qa.x, ka.x, acc[0]); acc[1] = fma2(qa.x, ka.y, acc[1]);
                acc[2] = fma2(qa.x, kb.x, acc[2]); acc[3] = fma2(qa.x, kb.y, acc[3]);
                acc[4] = fma2(qa.y, ka.x, acc[4]); acc[5] = fma2(qa.y, ka.y, acc[5]);
                acc[6] = fma2(qa.y, kb.x, acc[6]); acc[7] = fma2(qa.y, kb.y, acc[7]);
                acc[8] = fma2(qb.x, ka.x, acc[8]); acc[9] = fma2(qb.x, ka.y, acc[9]);
                acc[10]= fma2(qb.x, kb.x, acc[10]);acc[11]= fma2(qb.x, kb.y, acc[11]);
                acc[12]= fma2(qb.y, ka.x, acc[12]);acc[13]= fma2(qb.y, ka.y, acc[13]);
                acc[14]= fma2(qb.y, kb.x, acc[14]);acc[15]= fma2(qb.y, kb.y, acc[15]);
            }
            const float qn0 = sm[S_QN+q0], qn1 = sm[S_QN+q1];
            const float qn2 = sm[S_QN+q2], qn3 = sm[S_QN+q3];
            const float kn0 = sm[S_KN+k0], kn1 = sm[S_KN+k1];
            const float kn2 = sm[S_KN+k2i], kn3 = sm[S_KN+k3];
            const float pb0 = sm[S_PB+k0], pb1 = sm[S_PB+k1];
            const float pb2 = sm[S_PB+k2i], pb3 = sm[S_PB+k3];
            const int qv[4] = {q0,q1,q2,q3};
            const float qn[4] = {qn0,qn1,qn2,qn3};
            const int kv[4] = {k0,k1,k2i,k3};
            const float kn[4] = {kn0,kn1,kn2,kn3};
            const float pb[4] = {pb0,pb1,pb2,pb3};
            #pragma unroll
            for (int i = 0; i < 4; i++)
                #pragma unroll
                for (int j = 0; j < 4; j++) {
                    float s = hadd2(acc[i*4+j]);
                    float den = fmaxf(qn[i]*kn[j], 1e-6f);
                    float p = __expf(__fdividef(s, den) + pb[j]);
                    sm[S_Pp + (kv[j]>>1)*RS + qv[i]*2 + (kv[j]&1)] = p;
                }
        }
        __syncthreads();

        // ---- softmax denominator partials ----
        {
            const int q = t >> 2, quarter = t & 3;
            float s = 0.f;
            #pragma unroll
            for (int r = 0; r < 8; r++) {
                ull x = *(const ull*)(sm + S_Pp + (quarter*8 + r)*RS + q*2);
                s += hadd2(x);
            }
            sm[S_SQ + quarter*64 + q] = s;
        }
        // ---- PV: contraction over k via f32x2 lanes ----
        #pragma unroll 4
        for (int c2 = 0; c2 < 32; c2++) {
            ulonglong2 pa = Pa[c2*33], pb2 = Pb[c2*33];
            ulonglong2 va = Va[c2*33], vb = Vb[c2*33];
            oacc[0] = fma2(pa.x, va.x, oacc[0]); oacc[1] = fma2(pa.x, va.y, oacc[1]);
            oacc[2] = fma2(pa.x, vb.x, oacc[2]); oacc[3] = fma2(pa.x, vb.y, oacc[3]);
            oacc[4] = fma2(pa.y, va.x, oacc[4]); oacc[5] = fma2(pa.y, va.y, oacc[5]);
            oacc[6] = fma2(pa.y, vb.x, oacc[6]); oacc[7] = fma2(pa.y, vb.y, oacc[7]);
            oacc[8] = fma2(pb2.x, va.x, oacc[8]); oacc[9] = fma2(pb2.x, va.y, oacc[9]);
            oacc[10]= fma2(pb2.x, vb.x, oacc[10]);oacc[11]= fma2(pb2.x, vb.y, oacc[11]);
            oacc[12]= fma2(pb2.y, va.x, oacc[12]);oacc[13]= fma2(pb2.y, va.y, oacc[13]);
            oacc[14]= fma2(pb2.y, vb.x, oacc[14]);oacc[15]= fma2(pb2.y, vb.y, oacc[15]);
        }
        __syncthreads();
        if (t < 64)
            sm[S_L + t] += sm[S_SQ+t] + sm[S_SQ+64+t] + sm[S_SQ+128+t] + sm[S_SQ+192+t];
        __syncthreads();
    }

    // ---- finalize PV -> Op pair layout [dv2][q*2+(dv&1)] ----
    {
        const float i0 = 1.f/sm[S_L+q0], i1 = 1.f/sm[S_L+q1];
        const float i2 = 1.f/sm[S_L+q2], i3 = 1.f/sm[S_L+q3];
        const int qv[4] = {q0,q1,q2,q3};
        const float il[4] = {i0,i1,i2,i3};
        const int dv[4] = {k0,k1,k2i,k3};
        #pragma unroll
        for (int i = 0; i < 4; i++)
            #pragma unroll
            for (int j = 0; j < 4; j++)
                sm[S_Op + (dv[j]>>1)*RS + qv[i]*2 + (dv[j]&1)] = hadd2(oacc[i*4+j]) * il[i];
    }
    __syncthreads();

    // ---- output projection: 4 passes of 64 emb cols ----
    const ulonglong2* Oa = (const ulonglong2*)(sm + S_Op + qg*4);
    const ulonglong2* Ob = (const ulonglong2*)(sm + S_Op + qg*4 + 64);
    const ulonglong2* Ra = (const ulonglong2*)(sm + S_Rw + sg*4);
    const ulonglong2* Rb2 = (const ulonglong2*)(sm + S_Rw + sg*4 + 64);

    for (int pass = 0; pass < 4; pass++) {
        const int e0 = pass*64;
        // load Rw tile -> pair layout [dv2][e*2+(dv&1)]
        {
            const float2* Rsrc = (const float2*)(Rw + (size_t)e0*60);
            for (int idx = t; idx < 1920; idx += 256) {
                const int r = idx / 30;
                const int c = (idx - r*30) * 2;
                float2 rv = Rsrc[idx];
                *(float2*)(sm + S_Rw + (c>>1)*RS + r*2) = rv;
            }
        }
        __syncthreads();

        ull acc[16];
        #pragma unroll
        for (int z = 0; z < 16; z++) acc[z] = 0;
        #pragma unroll 4
        for (int d2 = 0; d2 < 32; d2++) {
            ulonglong2 oa = Oa[d2*33], ob = Ob[d2*33];
            ulonglong2 ra = Ra[d2*33], rb = Rb2[d2*33];
            acc[0] = fma2(oa.x, ra.x, acc[0]); acc[1] = fma2(oa.x, ra.y, acc[1]);
            acc[2] = fma2(oa.x, rb.x, acc[2]); acc[3] = fma2(oa.x, rb.y, acc[3]);
            acc[4] = fma2(oa.y, ra.x, acc[4]); acc[5] = fma2(oa.y, ra.y, acc[5]);
            acc[6] = fma2(oa.y, rb.x, acc[6]); acc[7] = fma2(oa.y, rb.y, acc[7]);
            acc[8] = fma2(ob.x, ra.x, acc[8]); acc[9] = fma2(ob.x, ra.y, acc[9]);
            acc[10]= fma2(ob.x, rb.x, acc[10]);acc[11]= fma2(ob.x, rb.y, acc[11]);
            acc[12]= fma2(ob.y, ra.x, acc[12]);acc[13]= fma2(ob.y, ra.y, acc[13]);
            acc[14]= fma2(ob.y, rb.x, acc[14]);acc[15]= fma2(ob.y, rb.y, acc[15]);
        }
        // stage into smem (stride-66 tile over the dead Pp region), coalesce out
        {
            const int qv[4] = {q0,q1,q2,q3};
            const int ev[4] = {k0,k1,k2i,k3};
            #pragma unroll
            for (int i = 0; i < 4; i++)
                #pragma unroll
                for (int j = 0; j < 4; j++)
                    sm[S_Pp + qv[i]*66 + ev[j]] = hadd2(acc[i*4+j]);
        }
        __syncthreads();
        for (int idx = t; idx < 4096; idx += 256) {
            const int r = idx >> 6, c = idx & 63;
            out[(size_t)(tok0 + r)*EMB + e0 + c] = sm[S_Pp + r*66 + c] + Rb[e0 + c];
        }
        __syncthreads();
    }
}

// ---------------------------------------------------------------------------
extern "C" void kernel_launch(void* const* d_in, const int* in_sizes, int n_in,
                              void* d_out, int out_size)
{
    (void)in_sizes; (void)n_in; (void)out_size;
    const int*   titems = (const int*)  d_in[0];
    const int*   citems = (const int*)  d_in[1];
    const float* tvec   = (const float*)d_in[2];
    const float* cvec   = (const float*)d_in[3];
    const float* Atw    = (const float*)d_in[4];
    const float* Atb    = (const float*)d_in[5];
    const float* Acw    = (const float*)d_in[6];
    const float* Acb    = (const float*)d_in[7];
    const float* Bcw    = (const float*)d_in[8];
    const float* Bcb    = (const float*)d_in[9];
    const float* pb     = (const float*)d_in[10];
    const float* Rw     = (const float*)d_in[11];
    const float* Rb     = (const float*)d_in[12];
    float* out = (float*)d_out;

    kv_proj_kernel<<<NTOK/32, 256>>>(citems, cvec, Acw, Acb, Bcw, Bcb);

    cudaFuncSetAttribute(att_kernel, cudaFuncAttributeMaxDynamicSharedMemorySize,
                         ATT_SMEM_BYTES);
    att_kernel<<<BATCH*(NTQ/64), 256, ATT_SMEM_BYTES>>>(
        titems, tvec, Atw, Atb, pb, Rw, Rb, out);
}

// round 5
// speedup vs baseline: 1.4287x; 1.2245x over previous
#include <cuda_runtime.h>
#include <mma.h>
#include <math.h>

using namespace nvcuda;

#define BATCH 128
#define NTQ   512
#define NCK   512
#define EMB   256
#define NTOK  (BATCH*NCK)

// ---- device scratch (allocation-free) ----
__device__ float g_K[NTOK*64];      // K padded to 64 dims (60..63 = 0)
__device__ float g_V[NTOK*64];      // V padded to 64 dims
__device__ float g_kn[NTOK];
__device__ float g_Wq[64*256];      // At_w zero-padded to 64 rows
__device__ float g_Wc[128*256];     // [Ac_w; pad4; Bc_w; pad4]
__device__ float g_Rp[256*64];      // R_w padded: [e][dv<60 ? Rw : 0]
__device__ float g_bq[64];
__device__ float g_bc[128];

template<typename F> __device__ __forceinline__ void cvt_tf32(F& f) {
    #pragma unroll
    for (int i = 0; i < f.num_elements; i++) f.x[i] = wmma::__float_to_tf32(f.x[i]);
}

typedef wmma::fragment<wmma::matrix_a, 16,16,8, wmma::precision::tf32, wmma::row_major> AFrag;
typedef wmma::fragment<wmma::matrix_b, 16,16,8, wmma::precision::tf32, wmma::col_major> BFragC;
typedef wmma::fragment<wmma::matrix_b, 16,16,8, wmma::precision::tf32, wmma::row_major> BFragR;
typedef wmma::fragment<wmma::accumulator, 16,16,8, float> CFrag;

// ---------------------------------------------------------------------------
// Prep: build zero-padded weight/bias copies so wmma B-operands load directly
// from global with clean leading dimensions.
// ---------------------------------------------------------------------------
__global__ void prep_kernel(const float* __restrict__ Atw, const float* __restrict__ Atb,
                            const float* __restrict__ Acw, const float* __restrict__ Acb,
                            const float* __restrict__ Bcw, const float* __restrict__ Bcb,
                            const float* __restrict__ Rw)
{
    const int i = blockIdx.x*blockDim.x + threadIdx.x;
    const int stride = gridDim.x*blockDim.x;
    for (int idx = i; idx < 64*256; idx += stride) {
        int d = idx >> 8, e = idx & 255;
        g_Wq[idx] = (d < 60) ? Atw[d*256+e] : 0.f;
    }
    for (int idx = i; idx < 128*256; idx += stride) {
        int d = idx >> 8, e = idx & 255;
        float v = 0.f;
        if (d < 60) v = Acw[d*256+e];
        else if (d >= 64 && d < 124) v = Bcw[(d-64)*256+e];
        g_Wc[idx] = v;
    }
    for (int idx = i; idx < 256*64; idx += stride) {
        int e = idx >> 6, dv = idx & 63;
        g_Rp[idx] = (dv < 60) ? Rw[e*60+dv] : 0.f;
    }
    if (i < 64)  g_bq[i] = (i < 60) ? Atb[i] : 0.f;
    if (i < 128) g_bc[i] = (i < 60) ? Acb[i] : ((i >= 64 && i < 124) ? Bcb[i-64] : 0.f);
}

// ---------------------------------------------------------------------------
// Kernel 1: K/V projection via tf32 wmma. Block = 64 ctx tokens, 256 threads.
// GEMM: cemb(64x256) @ Wc^T(256x128) -> [K|V] padded; + bias; norms.
// ---------------------------------------------------------------------------
#define KV_SMEM_FLOATS (16640 + 8448 + 64)
#define KV_SMEM_BYTES  (KV_SMEM_FLOATS*4)

__global__ __launch_bounds__(256) void kv_proj_w(
    const int* __restrict__ citems, const float* __restrict__ cvec)
{
    extern __shared__ float sm[];
    float* cemb = sm;              // 64 x 260
    float* outp = sm + 16640;      // 64 x 132
    int*   items = (int*)(sm + 16640 + 8448);

    const int t = threadIdx.x, lane = t & 31, w = t >> 5;
    const int base = blockIdx.x * 64;

    if (t < 64) items[t] = citems[base + t];
    __syncthreads();

    for (int r = w*8; r < w*8 + 8; r++) {
        const float4* src = (const float4*)(cvec + (size_t)items[r]*EMB);
        float4* dst = (float4*)(cemb + r*260);
        #pragma unroll
        for (int i = lane; i < 64; i += 32) dst[i] = src[i];
    }
    __syncthreads();

    // warp w: m-tile = w&3 (16 tokens), n-tiles = (w>>2)*4 .. +4 (64 dims)
    {
        const int tm = w & 3;
        const int ng = (w >> 2) * 4;
        CFrag acc[4];
        #pragma unroll
        for (int j = 0; j < 4; j++) wmma::fill_fragment(acc[j], 0.f);
        for (int k0 = 0; k0 < 256; k0 += 8) {
            AFrag af;
            wmma::load_matrix_sync(af, cemb + tm*16*260 + k0, 260);
            cvt_tf32(af);
            #pragma unroll
            for (int j = 0; j < 4; j++) {
                BFragC bf;
                wmma::load_matrix_sync(bf, g_Wc + (size_t)(ng+j)*16*256 + k0, 256);
                cvt_tf32(bf);
                wmma::mma_sync(acc[j], af, bf, acc[j]);
            }
        }
        #pragma unroll
        for (int j = 0; j < 4; j++)
            wmma::store_matrix_sync(outp + tm*16*132 + (ng+j)*16, acc[j], 132,
                                    wmma::mem_row_major);
    }
    __syncthreads();

    // bias + writeout (pad cols already zero: Wc pad rows & bc pad are zero)
    for (int idx = t; idx < 8192; idx += 256) {
        const int r = idx >> 7, c = idx & 127;
        float v = outp[r*132 + c] + g_bc[c];
        outp[r*132 + c] = v;
        if (c < 64) g_K[(size_t)(base + r)*64 + c]        = v;
        else        g_V[(size_t)(base + r)*64 + (c - 64)] = v;
    }
    __syncthreads();
    if (t < 64) {
        float s = 0.f;
        #pragma unroll 4
        for (int c = 0; c < 60; c++) { float v = outp[t*132 + c]; s += v*v; }
        g_kn[base + t] = sqrtf(s);
    }
}

// ---------------------------------------------------------------------------
// Kernel 2: fused Q-proj + cosine attention + output projection, all tf32 wmma.
// Block = (batch, 64-query tile), 256 threads.
// Warp tile map (4x4 tiles of 16x16 over 64x64): tm = w>>1, tn = (w&1)*2 + u.
// ---------------------------------------------------------------------------
#define AS_Q  0        // 64 x 68
#define AS_K  4352     // 64 x 68  (qemb overlay starts here: 64x260 = 16640 fl)
#define AS_V  8704
#define AS_P  13056
#define AS_O  17408
#define AS_QN 21760
#define AS_L  21824
#define AS_KN 21888
#define AS_PB 21952
#define AS_IT 22016
#define AS_SQ 22080    // 256
#define ATT_FLOATS 22336
#define ATT_SMEM_BYTES (ATT_FLOATS*4)

__global__ __launch_bounds__(256) void att_w(
    const int* __restrict__ titems, const float* __restrict__ tvec,
    const float* __restrict__ pos_bias, const float* __restrict__ Rb,
    float* __restrict__ out)
{
    extern __shared__ float sm[];
    const int t = threadIdx.x, lane = t & 31, w = t >> 5;
    const int b  = blockIdx.x >> 3;
    const int qt = blockIdx.x & 7;
    const int tok0 = b*NTQ + qt*64;

    const int tm  = w >> 1;          // m-tile (queries)
    const int tn0 = (w & 1) * 2;     // first of two n-tiles

    int* it_s = (int*)(sm + AS_IT);
    if (t < 64) it_s[t] = titems[tok0 + t];
    __syncthreads();

    // gather 64 query embedding rows into overlay region
    float* qemb = sm + AS_K;         // 64 x 260
    for (int r = w*8; r < w*8 + 8; r++) {
        const float4* src = (const float4*)(tvec + (size_t)it_s[r]*EMB);
        float4* dst = (float4*)(qemb + r*260);
        #pragma unroll
        for (int i = lane; i < 64; i += 32) dst[i] = src[i];
    }
    __syncthreads();

    // ---- Q projection: qemb(64x256) @ Wq^T -> S_Q (64x64 padded, ld 68) ----
    {
        CFrag acc[2];
        wmma::fill_fragment(acc[0], 0.f);
        wmma::fill_fragment(acc[1], 0.f);
        for (int k0 = 0; k0 < 256; k0 += 8) {
            AFrag af;
            wmma::load_matrix_sync(af, qemb + tm*16*260 + k0, 260);
            cvt_tf32(af);
            #pragma unroll
            for (int u = 0; u < 2; u++) {
                BFragC bf;
                wmma::load_matrix_sync(bf, g_Wq + (size_t)(tn0+u)*16*256 + k0, 256);
                cvt_tf32(bf);
                wmma::mma_sync(acc[u], af, bf, acc[u]);
            }
        }
        #pragma unroll
        for (int u = 0; u < 2; u++)
            wmma::store_matrix_sync(sm + AS_Q + tm*16*68 + (tn0+u)*16, acc[u], 68,
                                    wmma::mem_row_major);
    }
    __syncthreads();
    // bias (pad cols zero), then query norms
    for (int idx = t; idx < 4096; idx += 256) {
        const int r = idx >> 6, c = idx & 63;
        sm[AS_Q + r*68 + c] += g_bq[c];
    }
    __syncthreads();
    if (t < 64) {
        float s = 0.f;
        #pragma unroll 4
        for (int c = 0; c < 64; c++) { float v = sm[AS_Q + t*68 + c]; s += v*v; }
        sm[AS_QN + t] = sqrtf(s);
        sm[AS_L + t] = 0.f;
    }
    __syncthreads();

    CFrag oacc[2];
    wmma::fill_fragment(oacc[0], 0.f);
    wmma::fill_fragment(oacc[1], 0.f);

    for (int kt = 0; kt < 8; kt++) {
        // ---- load K/V tiles (coalesced 64-float rows; pads already zero) ----
        {
            const size_t gb = (size_t)(b*NCK + kt*64) * 64;
            for (int idx = t; idx < 4096; idx += 256) {
                const int r = idx >> 6, c = idx & 63;
                sm[AS_K + r*68 + c] = g_K[gb + idx];
                sm[AS_V + r*68 + c] = g_V[gb + idx];
            }
            if (t < 64) {
                sm[AS_KN + t] = g_kn[b*NCK + kt*64 + t];
                sm[AS_PB + t] = pos_bias[kt*64 + t];
            }
        }
        __syncthreads();

        // ---- scores: Q(64x64) @ K^T -> S_P ----
        {
            CFrag acc[2];
            wmma::fill_fragment(acc[0], 0.f);
            wmma::fill_fragment(acc[1], 0.f);
            for (int k0 = 0; k0 < 64; k0 += 8) {
                AFrag af;
                wmma::load_matrix_sync(af, sm + AS_Q + tm*16*68 + k0, 68);
                cvt_tf32(af);
                #pragma unroll
                for (int u = 0; u < 2; u++) {
                    BFragC bf;
                    wmma::load_matrix_sync(bf, sm + AS_K + (tn0+u)*16*68 + k0, 68);
                    cvt_tf32(bf);
                    wmma::mma_sync(acc[u], af, bf, acc[u]);
                }
            }
            #pragma unroll
            for (int u = 0; u < 2; u++)
                wmma::store_matrix_sync(sm + AS_P + tm*16*68 + (tn0+u)*16, acc[u], 68,
                                        wmma::mem_row_major);
        }
        __syncthreads();

        // ---- normalize + exp (no max-subtract: |cos|<=~1, bias tiny) ----
        {
            const int q = t >> 2, qa = t & 3;
            const float qn = sm[AS_QN + q];
            float s = 0.f;
            #pragma unroll
            for (int j = 0; j < 16; j++) {
                const int k = qa*16 + j;
                const float den = fmaxf(qn * sm[AS_KN + k], 1e-6f);
                const float p = __expf(__fdividef(sm[AS_P + q*68 + k], den) + sm[AS_PB + k]);
                sm[AS_P + q*68 + k] = p;
                s += p;
            }
            sm[AS_SQ + qa*64 + q] = s;
        }
        __syncthreads();

        // ---- PV: P(64x64) @ V(64x64) accumulated across kt ----
        for (int k0 = 0; k0 < 64; k0 += 8) {
            AFrag af;
            wmma::load_matrix_sync(af, sm + AS_P + tm*16*68 + k0, 68);
            cvt_tf32(af);
            #pragma unroll
            for (int u = 0; u < 2; u++) {
                BFragR bf;
                wmma::load_matrix_sync(bf, sm + AS_V + k0*68 + (tn0+u)*16, 68);
                cvt_tf32(bf);
                wmma::mma_sync(oacc[u], af, bf, oacc[u]);
            }
        }
        // softmax denominator accumulation (reads AS_SQ only)
        if (t < 64)
            sm[AS_L + t] += sm[AS_SQ + t] + sm[AS_SQ + 64 + t]
                          + sm[AS_SQ + 128 + t] + sm[AS_SQ + 192 + t];
        __syncthreads();
    }

    // ---- finalize PV -> S_O, divide by L ----
    #pragma unroll
    for (int u = 0; u < 2; u++)
        wmma::store_matrix_sync(sm + AS_O + tm*16*68 + (tn0+u)*16, oacc[u], 68,
                                wmma::mem_row_major);
    __syncthreads();
    if (t < 64) sm[AS_QN + t] = 1.f / sm[AS_L + t];   // reuse QN as invL
    __syncthreads();
    for (int idx = t; idx < 4096; idx += 256) {
        const int r = idx >> 6, c = idx & 63;
        sm[AS_O + r*68 + c] *= sm[AS_QN + r];
    }
    __syncthreads();

    // ---- output projection: O(64x64) @ Rp^T(64x256) in 4 chunks of 64 ----
    for (int chunk = 0; chunk < 4; chunk++) {
        CFrag acc[2];
        wmma::fill_fragment(acc[0], 0.f);
        wmma::fill_fragment(acc[1], 0.f);
        for (int k0 = 0; k0 < 64; k0 += 8) {
            AFrag af;
            wmma::load_matrix_sync(af, sm + AS_O + tm*16*68 + k0, 68);
            cvt_tf32(af);
            #pragma unroll
            for (int u = 0; u < 2; u++) {
                BFragC bf;
                wmma::load_matrix_sync(bf, g_Rp + (size_t)(chunk*64 + (tn0+u)*16)*64 + k0, 64);
                cvt_tf32(bf);
                wmma::mma_sync(acc[u], af, bf, acc[u]);
            }
        }
        #pragma unroll
        for (int u = 0; u < 2; u++)
            wmma::store_matrix_sync(sm + AS_P + tm*16*68 + (tn0+u)*16, acc[u], 68,
                                    wmma::mem_row_major);
        __syncthreads();
        const int e0 = chunk*64;
        for (int idx = t; idx < 4096; idx += 256) {
            const int r = idx >> 6, c = idx & 63;
            out[(size_t)(tok0 + r)*EMB + e0 + c] = sm[AS_P + r*68 + c] + Rb[e0 + c];
        }
        __syncthreads();
    }
}

// ---------------------------------------------------------------------------
extern "C" void kernel_launch(void* const* d_in, const int* in_sizes, int n_in,
                              void* d_out, int out_size)
{
    (void)in_sizes; (void)n_in; (void)out_size;
    const int*   titems = (const int*)  d_in[0];
    const int*   citems = (const int*)  d_in[1];
    const float* tvec   = (const float*)d_in[2];
    const float* cvec   = (const float*)d_in[3];
    const float* Atw    = (const float*)d_in[4];
    const float* Atb    = (const float*)d_in[5];
    const float* Acw    = (const float*)d_in[6];
    const float* Acb    = (const float*)d_in[7];
    const float* Bcw    = (const float*)d_in[8];
    const float* Bcb    = (const float*)d_in[9];
    const float* pb     = (const float*)d_in[10];
    const float* Rw     = (const float*)d_in[11];
    const float* Rb     = (const float*)d_in[12];
    float* out = (float*)d_out;

    prep_kernel<<<128, 256>>>(Atw, Atb, Acw, Acb, Bcw, Bcb, Rw);

    cudaFuncSetAttribute(kv_proj_w, cudaFuncAttributeMaxDynamicSharedMemorySize,
                         KV_SMEM_BYTES);
    kv_proj_w<<<NTOK/64, 256, KV_SMEM_BYTES>>>(citems, cvec);

    cudaFuncSetAttribute(att_w, cudaFuncAttributeMaxDynamicSharedMemorySize,
                         ATT_SMEM_BYTES);
    att_w<<<BATCH*(NTQ/64), 256, ATT_SMEM_BYTES>>>(titems, tvec, pb, Rb, out);
}

// round 9
// speedup vs baseline: 1.7204x; 1.2041x over previous
#include <cuda_runtime.h>
#include <mma.h>
#include <math.h>

using namespace nvcuda;

#define BATCH 128
#define NTQ   512
#define NCK   512
#define EMB   256
#define NTOK  (BATCH*NCK)

// ---- device scratch (allocation-free) ----
__device__ float g_K[NTOK*64];      // K padded to 64 dims (60..63 = 0)
__device__ float g_V[NTOK*64];      // V padded to 64 dims
__device__ float g_ikn[NTOK];       // inverse key norms
__device__ float g_Wq[64*256];      // At_w zero-padded to 64 rows
__device__ float g_Wc[128*256];     // [Ac_w; pad4; Bc_w; pad4]
__device__ float g_Rp[256*64];      // R_w padded: [e][dv<60 ? Rw : 0]
__device__ float g_bq[64];
__device__ float g_bc[128];

template<typename F> __device__ __forceinline__ void cvt_tf32(F& f) {
    #pragma unroll
    for (int i = 0; i < f.num_elements; i++) f.x[i] = wmma::__float_to_tf32(f.x[i]);
}

typedef wmma::fragment<wmma::matrix_a, 16,16,8, wmma::precision::tf32, wmma::row_major> AFrag;
typedef wmma::fragment<wmma::matrix_b, 16,16,8, wmma::precision::tf32, wmma::col_major> BFragC;
typedef wmma::fragment<wmma::matrix_b, 16,16,8, wmma::precision::tf32, wmma::row_major> BFragR;
typedef wmma::fragment<wmma::accumulator, 16,16,8, float> CFrag;

// ---------------------------------------------------------------------------
__global__ void prep_kernel(const float* __restrict__ Atw, const float* __restrict__ Atb,
                            const float* __restrict__ Acw, const float* __restrict__ Acb,
                            const float* __restrict__ Bcw, const float* __restrict__ Bcb,
                            const float* __restrict__ Rw)
{
    const int i = blockIdx.x*blockDim.x + threadIdx.x;
    const int stride = gridDim.x*blockDim.x;
    for (int idx = i; idx < 64*256; idx += stride) {
        int d = idx >> 8, e = idx & 255;
        g_Wq[idx] = (d < 60) ? Atw[d*256+e] : 0.f;
    }
    for (int idx = i; idx < 128*256; idx += stride) {
        int d = idx >> 8, e = idx & 255;
        float v = 0.f;
        if (d < 60) v = Acw[d*256+e];
        else if (d >= 64 && d < 124) v = Bcw[(d-64)*256+e];
        g_Wc[idx] = v;
    }
    for (int idx = i; idx < 256*64; idx += stride) {
        int e = idx >> 6, dv = idx & 63;
        g_Rp[idx] = (dv < 60) ? Rw[e*60+dv] : 0.f;
    }
    if (i < 64)  g_bq[i] = (i < 60) ? Atb[i] : 0.f;
    if (i < 128) g_bc[i] = (i < 60) ? Acb[i] : ((i >= 64 && i < 124) ? Bcb[i-64] : 0.f);
}

// ---------------------------------------------------------------------------
// Kernel 1: K/V projection. 128 tokens/block, 512 blocks, 256 threads.
// GEMM cemb(128x256) @ Wc^T -> 128x128. Warp: 2 m-tiles x 4 n-tiles (8 frags),
// so each warp reads only half of B rows (4x redundancy instead of 8x).
// ---------------------------------------------------------------------------
#define KV_CEMB 0                    // 128 x 260
#define KV_OUT  33280                // 128 x 132
#define KV_IT   (33280+16896)        // 128 ints
#define KV_SMEM_BYTES ((33280+16896+128)*4)

__global__ __launch_bounds__(256) void kv_proj_w(
    const int* __restrict__ citems, const float* __restrict__ cvec)
{
    extern __shared__ float sm[];
    float* cemb = sm + KV_CEMB;
    float* outp = sm + KV_OUT;
    int*   items = (int*)(sm + KV_IT);

    const int t = threadIdx.x, lane = t & 31, w = t >> 5;
    const int base = blockIdx.x * 128;

    if (t < 128) items[t] = citems[base + t];
    __syncthreads();

    for (int r = w*16; r < w*16 + 16; r++) {
        const float4* src = (const float4*)(cvec + (size_t)items[r]*EMB);
        float4* dst = (float4*)(cemb + r*260);
        #pragma unroll
        for (int i = lane; i < 64; i += 32) dst[i] = src[i];
    }
    __syncthreads();

    {
        const int ma = w & 3;            // m-tiles ma and ma+4
        const int ng = (w >> 2) * 4;     // n-tiles ng..ng+3
        CFrag acc[2][4];
        #pragma unroll
        for (int m = 0; m < 2; m++)
            #pragma unroll
            for (int j = 0; j < 4; j++) wmma::fill_fragment(acc[m][j], 0.f);
        for (int k0 = 0; k0 < 256; k0 += 8) {
            AFrag a0, a1;
            wmma::load_matrix_sync(a0, cemb + ma*16*260 + k0, 260);
            wmma::load_matrix_sync(a1, cemb + (ma+4)*16*260 + k0, 260);
            cvt_tf32(a0); cvt_tf32(a1);
            #pragma unroll
            for (int j = 0; j < 4; j++) {
                BFragC bf;
                wmma::load_matrix_sync(bf, g_Wc + (size_t)(ng+j)*16*256 + k0, 256);
                cvt_tf32(bf);
                wmma::mma_sync(acc[0][j], a0, bf, acc[0][j]);
                wmma::mma_sync(acc[1][j], a1, bf, acc[1][j]);
            }
        }
        #pragma unroll
        for (int m = 0; m < 2; m++)
            #pragma unroll
            for (int j = 0; j < 4; j++)
                wmma::store_matrix_sync(outp + (ma + m*4)*16*132 + (ng+j)*16,
                                        acc[m][j], 132, wmma::mem_row_major);
    }
    __syncthreads();

    for (int idx = t; idx < 16384; idx += 256) {
        const int r = idx >> 7, c = idx & 127;
        float v = outp[r*132 + c] + g_bc[c];
        outp[r*132 + c] = v;
        if (c < 64) g_K[(size_t)(base + r)*64 + c]        = v;
        else        g_V[(size_t)(base + r)*64 + (c - 64)] = v;
    }
    __syncthreads();
    if (t < 128) {
        float s = 0.f;
        #pragma unroll 4
        for (int c = 0; c < 60; c++) { float v = outp[t*132 + c]; s += v*v; }
        g_ikn[base + t] = rsqrtf(s);
    }
}

// ---------------------------------------------------------------------------
// Kernel 2: fused attention. 128 queries/block, 512 blocks, 256 threads.
// Inverse-norm multiplies (no RCP), tf32 wmma everywhere.
// ---------------------------------------------------------------------------
#define AS_Q  0        // 128 x 68
#define AS_K  8704     // 64 x 68   (qemb half-staging overlays K..P start)
#define AS_V  13056    // 64 x 68
#define AS_P  17408    // 128 x 68
#define AS_O  8704     // overlay on K+V after kt loop (128 x 68)
#define AS_QN 26112    // 128 (inv q-norm, later inv L)
#define AS_L  26240    // 128
#define AS_KN 26368    // 64 (inv k-norm)
#define AS_PB 26432    // 64
#define AS_IT 26496    // 128 ints
#define AS_SQ 26624    // 256
#define ATT_FLOATS 26880
#define ATT_SMEM_BYTES (ATT_FLOATS*4)

__global__ __launch_bounds__(256) void att_w(
    const int* __restrict__ titems, const float* __restrict__ tvec,
    const float* __restrict__ pos_bias, const float* __restrict__ Rb,
    float* __restrict__ out)
{
    extern __shared__ float sm[];
    const int t = threadIdx.x, lane = t & 31, w = t >> 5;
    const int b  = blockIdx.x >> 2;
    const int qt = blockIdx.x & 3;
    const int tok0 = b*NTQ + qt*128;

    int* it_s = (int*)(sm + AS_IT);
    if (t < 128) it_s[t] = titems[tok0 + t];
    __syncthreads();

    // ---- Q projection in two 64-row halves (gather staged over K/V/P) ----
    float* qemb = sm + AS_K;   // 64 x 260 = 16640 fl, fits in [8704, 26112)
    for (int h = 0; h < 2; h++) {
        for (int r = w*8; r < w*8 + 8; r++) {
            const float4* src = (const float4*)(tvec + (size_t)it_s[h*64 + r]*EMB);
            float4* dst = (float4*)(qemb + r*260);
            #pragma unroll
            for (int i = lane; i < 64; i += 32) dst[i] = src[i];
        }
        __syncthreads();
        {
            const int tm = w >> 1, tn0 = (w & 1) * 2;
            CFrag acc[2];
            wmma::fill_fragment(acc[0], 0.f);
            wmma::fill_fragment(acc[1], 0.f);
            for (int k0 = 0; k0 < 256; k0 += 8) {
                AFrag af;
                wmma::load_matrix_sync(af, qemb + tm*16*260 + k0, 260);
                cvt_tf32(af);
                #pragma unroll
                for (int u = 0; u < 2; u++) {
                    BFragC bf;
                    wmma::load_matrix_sync(bf, g_Wq + (size_t)(tn0+u)*16*256 + k0, 256);
                    cvt_tf32(bf);
                    wmma::mma_sync(acc[u], af, bf, acc[u]);
                }
            }
            #pragma unroll
            for (int u = 0; u < 2; u++)
                wmma::store_matrix_sync(sm + AS_Q + (h*64 + tm*16)*68 + (tn0+u)*16,
                                        acc[u], 68, wmma::mem_row_major);
        }
        __syncthreads();
    }
    // bias + inverse query norms
    for (int idx = t; idx < 8192; idx += 256) {
        const int r = idx >> 6, c = idx & 63;
        sm[AS_Q + r*68 + c] += g_bq[c];
    }
    __syncthreads();
    if (t < 128) {
        float s = 0.f;
        #pragma unroll 4
        for (int c = 0; c < 64; c++) { float v = sm[AS_Q + t*68 + c]; s += v*v; }
        sm[AS_QN + t] = rsqrtf(s);
        sm[AS_L + t] = 0.f;
    }
    __syncthreads();

    CFrag oacc[4];
    #pragma unroll
    for (int j = 0; j < 4; j++) wmma::fill_fragment(oacc[j], 0.f);

    for (int kt = 0; kt < 8; kt++) {
        // ---- load K/V tiles ----
        {
            const size_t gb = (size_t)(b*NCK + kt*64) * 64;
            for (int idx = t; idx < 4096; idx += 256) {
                const int r = idx >> 6, c = idx & 63;
                sm[AS_K + r*68 + c] = g_K[gb + idx];
                sm[AS_V + r*68 + c] = g_V[gb + idx];
            }
            if (t < 64) {
                sm[AS_KN + t] = g_ikn[b*NCK + kt*64 + t];
                sm[AS_PB + t] = pos_bias[kt*64 + t];
            }
        }
        __syncthreads();

        // ---- scores: Q(128x64) @ K^T; warp = m-tile w, 4 n-tiles ----
        {
            CFrag acc[4];
            #pragma unroll
            for (int j = 0; j < 4; j++) wmma::fill_fragment(acc[j], 0.f);
            for (int k0 = 0; k0 < 64; k0 += 8) {
                AFrag af;
                wmma::load_matrix_sync(af, sm + AS_Q + w*16*68 + k0, 68);
                cvt_tf32(af);
                #pragma unroll
                for (int j = 0; j < 4; j++) {
                    BFragC bf;
                    wmma::load_matrix_sync(bf, sm + AS_K + j*16*68 + k0, 68);
                    cvt_tf32(bf);
                    wmma::mma_sync(acc[j], af, bf, acc[j]);
                }
            }
            #pragma unroll
            for (int j = 0; j < 4; j++)
                wmma::store_matrix_sync(sm + AS_P + w*16*68 + j*16, acc[j], 68,
                                        wmma::mem_row_major);
        }
        __syncthreads();

        // ---- normalize (inverse multiplies) + exp ----
        {
            const int q = t >> 1, ha = t & 1;
            const float iq = sm[AS_QN + q];
            float s = 0.f;
            #pragma unroll
            for (int j = 0; j < 32; j++) {
                const int k = ha*32 + j;
                const float p = __expf(sm[AS_P + q*68 + k] * (iq * sm[AS_KN + k])
                                       + sm[AS_PB + k]);
                sm[AS_P + q*68 + k] = p;
                s += p;
            }
            sm[AS_SQ + ha*128 + q] = s;
        }
        __syncthreads();

        // ---- PV accumulate ----
        for (int k0 = 0; k0 < 64; k0 += 8) {
            AFrag af;
            wmma::load_matrix_sync(af, sm + AS_P + w*16*68 + k0, 68);
            cvt_tf32(af);
            #pragma unroll
            for (int j = 0; j < 4; j++) {
                BFragR bf;
                wmma::load_matrix_sync(bf, sm + AS_V + k0*68 + j*16, 68);
                cvt_tf32(bf);
                wmma::mma_sync(oacc[j], af, bf, oacc[j]);
            }
        }
        if (t < 128)
            sm[AS_L + t] += sm[AS_SQ + t] + sm[AS_SQ + 128 + t];
        __syncthreads();
    }

    // ---- finalize: O = oacc / L (O overlays K/V region) ----
    #pragma unroll
    for (int j = 0; j < 4; j++)
        wmma::store_matrix_sync(sm + AS_O + w*16*68 + j*16, oacc[j], 68,
                                wmma::mem_row_major);
    __syncthreads();
    if (t < 128) sm[AS_QN + t] = 1.f / sm[AS_L + t];
    __syncthreads();
    for (int idx = t; idx < 8192; idx += 256) {
        const int r = idx >> 6, c = idx & 63;
        sm[AS_O + r*68 + c] *= sm[AS_QN + r];
    }
    __syncthreads();

    // ---- output projection: O(128x64) @ Rp^T in 4 chunks of 64 cols ----
    for (int chunk = 0; chunk < 4; chunk++) {
        CFrag acc[4];
        #pragma unroll
        for (int j = 0; j < 4; j++) wmma::fill_fragment(acc[j], 0.f);
        for (int k0 = 0; k0 < 64; k0 += 8) {
            AFrag af;
            wmma::load_matrix_sync(af, sm + AS_O + w*16*68 + k0, 68);
            cvt_tf32(af);
            #pragma unroll
            for (int j = 0; j < 4; j++) {
                BFragC bf;
                wmma::load_matrix_sync(bf, g_Rp + (size_t)(chunk*64 + j*16)*64 + k0, 64);
                cvt_tf32(bf);
                wmma::mma_sync(acc[j], af, bf, acc[j]);
            }
        }
        #pragma unroll
        for (int j = 0; j < 4; j++)
            wmma::store_matrix_sync(sm + AS_P + w*16*68 + j*16, acc[j], 68,
                                    wmma::mem_row_major);
        __syncthreads();
        const int e0 = chunk*64;
        for (int idx = t; idx < 8192; idx += 256) {
            const int r = idx >> 6, c = idx & 63;
            out[(size_t)(tok0 + r)*EMB + e0 + c] = sm[AS_P + r*68 + c] + Rb[e0 + c];
        }
        __syncthreads();
    }
}

// ---------------------------------------------------------------------------
extern "C" void kernel_launch(void* const* d_in, const int* in_sizes, int n_in,
                              void* d_out, int out_size)
{
    (void)in_sizes; (void)n_in; (void)out_size;
    const int*   titems = (const int*)  d_in[0];
    const int*   citems = (const int*)  d_in[1];
    const float* tvec   = (const float*)d_in[2];
    const float* cvec   = (const float*)d_in[3];
    const float* Atw    = (const float*)d_in[4];
    const float* Atb    = (const float*)d_in[5];
    const float* Acw    = (const float*)d_in[6];
    const float* Acb    = (const float*)d_in[7];
    const float* Bcw    = (const float*)d_in[8];
    const float* Bcb    = (const float*)d_in[9];
    const float* pb     = (const float*)d_in[10];
    const float* Rw     = (const float*)d_in[11];
    const float* Rb     = (const float*)d_in[12];
    float* out = (float*)d_out;

    prep_kernel<<<128, 256>>>(Atw, Atb, Acw, Acb, Bcw, Bcb, Rw);

    cudaFuncSetAttribute(kv_proj_w, cudaFuncAttributeMaxDynamicSharedMemorySize,
                         KV_SMEM_BYTES);
    kv_proj_w<<<NTOK/128, 256, KV_SMEM_BYTES>>>(citems, cvec);

    cudaFuncSetAttribute(att_w, cudaFuncAttributeMaxDynamicSharedMemorySize,
                         ATT_SMEM_BYTES);
    att_w<<<BATCH*(NTQ/128), 256, ATT_SMEM_BYTES>>>(titems, tvec, pb, Rb, out);
}